// round 1
// baseline (speedup 1.0000x reference)
#include <cuda_runtime.h>
#include <math.h>

#define NB 64
#define NNODES 1296
#define NCLS 43
#define ODIM 16
#define NCO 688                 // 43*16
#define PRI_STRIDE (NNODES*NCO) // 891648

// ---------------- scratch (static device arrays; no allocation) ----------------
__device__ float g_cw[62208];        // conv1_w transposed [c][ky][kx][oc]
__device__ float g_pw[2097152];      // prim_w  transposed [ky][kx][ic][oc]
__device__ float g_h[9437184];       // conv1 out NHWC [b][y][x][oc]
__device__ float g_u[NB*NNODES*8];   // squashed primary caps [b][node][i]
__device__ float g_priors[57065472]; // [b][n][c][o]  (228 MB)
__device__ float g_outv[NB*NCO];     // outputs vector (b, c, o) — reused per iter
__device__ float g_delta0[NB*NNODES*NCLS];
__device__ float g_part[NB*16*NCO];  // per-chunk partial sums of s

// ---------------- weight transposes ----------------
__global__ void k_tcw(const float* __restrict__ w) {
    int i = blockIdx.x*256 + threadIdx.x;
    if (i < 62208) {
        int kx = i % 9, t1 = i / 9;
        int ky = t1 % 9, t2 = t1 / 9;
        int c  = t2 % 3, oc = t2 / 3;
        g_cw[((c*9+ky)*9+kx)*256 + oc] = w[i];
    }
}
__global__ void k_tpw(const float* __restrict__ w) {
    int i = blockIdx.x*256 + threadIdx.x;
    if (i < 2097152) {
        int kx = i & 7, ky = (i >> 3) & 7, ic = (i >> 6) & 255, oc = i >> 14;
        g_pw[(((ky*8+kx) << 8) + ic)*128 + oc] = w[i];
    }
}

// ---------------- conv1: 9x9 valid, relu. block=(y,b), thread=oc ----------------
__global__ void __launch_bounds__(256) k_conv1(const float* __restrict__ x,
                                               const float* __restrict__ cb) {
    const int y = blockIdx.x, b = blockIdx.y, oc = threadIdx.x;
    __shared__ float si[864];   // 3 ch x 9 rows x 32 cols
    for (int i = threadIdx.x; i < 864; i += 256) {
        int c = i / 288, rm = i % 288, r = rm >> 5, col = rm & 31;
        si[i] = x[((b*3 + c)*32 + (y + r))*32 + col];
    }
    __syncthreads();
    float acc[24];
#pragma unroll
    for (int i = 0; i < 24; i++) acc[i] = 0.f;
#pragma unroll 1
    for (int cky = 0; cky < 27; cky++) {        // cky = c*9+ky
        float w[9];
#pragma unroll
        for (int kx = 0; kx < 9; kx++) w[kx] = g_cw[(cky*9+kx)*256 + oc];
        float im[32];
        const float* rp = &si[cky*32];
#pragma unroll
        for (int j = 0; j < 32; j++) im[j] = rp[j];
#pragma unroll
        for (int xx = 0; xx < 24; xx++)
#pragma unroll
            for (int kx = 0; kx < 9; kx++) acc[xx] += w[kx]*im[xx+kx];
    }
    float bb = cb[oc];
#pragma unroll
    for (int xx = 0; xx < 24; xx++)
        g_h[((b*24+y)*24+xx)*256 + oc] = fmaxf(acc[xx] + bb, 0.f);
}

// ------- prim conv as implicit GEMM: M=5184(b,oy,ox) N=128(oc) K=16384(ky,kx,ic)
// epilogue fuses +bias and squash -> g_u
__global__ void __launch_bounds__(256) k_prim(const float* __restrict__ pb) {
    const int t  = threadIdx.x;
    const int m0 = blockIdx.x * 32;
    __shared__ float sA[32*33];   // [kk][m], pad 33
    __shared__ float sB[32*128];  // [kk][n]

    const int m_l = t >> 3;             // 0..31  (A-load row)
    const int k_l = (t & 7) << 2;       // 0,4..28 (A-load k offset)
    const int am  = m0 + m_l;
    const int ab  = am / 81;
    const int ar  = am % 81;
    const int aoy = ar / 9, aox = ar % 9;
    const int mb  = (t >> 5) << 2;      // compute tile rows
    const int nb  = (t & 31) << 2;      // compute tile cols

    float acc[4][4];
#pragma unroll
    for (int i = 0; i < 4; i++)
#pragma unroll
        for (int j = 0; j < 4; j++) acc[i][j] = 0.f;

    float4 ra, rb[4];
    // prologue: stage 0
    {
        int k = k_l;
        int pix = k >> 8, ic = k & 255;
        int ky = pix >> 3, kx = pix & 7;
        ra = *(const float4*)&g_h[(((ab*24 + 2*aoy+ky)*24 + 2*aox+kx) << 8) + ic];
#pragma unroll
        for (int j = 0; j < 4; j++) {
            int idx = t + j*256;
            rb[j] = *(const float4*)&g_pw[(idx >> 5)*128 + (idx & 31)*4];
        }
    }

    for (int s = 0; s < 512; s++) {
        // commit prefetched regs to smem
#pragma unroll
        for (int j = 0; j < 4; j++) sA[(k_l+j)*33 + m_l] = ((float*)&ra)[j];
#pragma unroll
        for (int j = 0; j < 4; j++) {
            int idx = t + j*256;
            *(float4*)&sB[(idx >> 5)*128 + (idx & 31)*4] = rb[j];
        }
        __syncthreads();
        if (s + 1 < 512) {   // prefetch next stage (overlaps compute)
            int k0 = (s+1) << 5;
            int k  = k0 + k_l;
            int pix = k >> 8, ic = k & 255;
            int ky = pix >> 3, kx = pix & 7;
            ra = *(const float4*)&g_h[(((ab*24 + 2*aoy+ky)*24 + 2*aox+kx) << 8) + ic];
#pragma unroll
            for (int j = 0; j < 4; j++) {
                int idx = t + j*256;
                rb[j] = *(const float4*)&g_pw[(k0 + (idx >> 5))*128 + (idx & 31)*4];
            }
        }
#pragma unroll
        for (int kk = 0; kk < 32; kk++) {
            float a0 = sA[kk*33 + mb + 0];
            float a1 = sA[kk*33 + mb + 1];
            float a2 = sA[kk*33 + mb + 2];
            float a3 = sA[kk*33 + mb + 3];
            float4 bv = *(float4*)&sB[kk*128 + nb];
            acc[0][0] += a0*bv.x; acc[0][1] += a0*bv.y; acc[0][2] += a0*bv.z; acc[0][3] += a0*bv.w;
            acc[1][0] += a1*bv.x; acc[1][1] += a1*bv.y; acc[1][2] += a1*bv.z; acc[1][3] += a1*bv.w;
            acc[2][0] += a2*bv.x; acc[2][1] += a2*bv.y; acc[2][2] += a2*bv.z; acc[2][3] += a2*bv.w;
            acc[3][0] += a3*bv.x; acc[3][1] += a3*bv.y; acc[3][2] += a3*bv.z; acc[3][3] += a3*bv.w;
        }
        __syncthreads();
    }

    // epilogue: +bias into smem P tile, then squash 8-vectors -> g_u
    float4 b4 = *(const float4*)&pb[nb];
#pragma unroll
    for (int i = 0; i < 4; i++) {
        sB[(mb+i)*128 + nb + 0] = acc[i][0] + b4.x;
        sB[(mb+i)*128 + nb + 1] = acc[i][1] + b4.y;
        sB[(mb+i)*128 + nb + 2] = acc[i][2] + b4.z;
        sB[(mb+i)*128 + nb + 3] = acc[i][3] + b4.w;
    }
    __syncthreads();
#pragma unroll
    for (int ii = 0; ii < 2; ii++) {
        int idx = t + ii*256;                 // < 512 = 32 rows * 16 d
        int row = idx >> 4, d = idx & 15;
        float p[8]; float sn = 0.f;
#pragma unroll
        for (int i = 0; i < 8; i++) { p[i] = sB[row*128 + i*16 + d]; sn += p[i]*p[i]; }
        float sc = sqrtf(sn) / (1.f + sn);    // squash scale
        int m = m0 + row, bb2 = m / 81, rr = m % 81;
        float* up = &g_u[((bb2*NNODES) + d*81 + rr)*8];
        float4 v0 = make_float4(p[0]*sc, p[1]*sc, p[2]*sc, p[3]*sc);
        float4 v1 = make_float4(p[4]*sc, p[5]*sc, p[6]*sc, p[7]*sc);
        *(float4*)up = v0; *(float4*)(up+4) = v1;
    }
}

// ------- priors[b,n,c,o] = sum_i u[b,n,i] * W[n,c,i,o]; block per node -------
__global__ void __launch_bounds__(704) k_priors(const float* __restrict__ rw) {
    int n = blockIdx.x, t = threadIdx.x;
    __shared__ float su[512];    // u for all 64 b at this node
    __shared__ float sw[5504];   // W slice [c][i][o]
    for (int i = t; i < 5504; i += 704) sw[i] = rw[n*5504 + i];
    for (int i = t; i < 512;  i += 704) su[i] = g_u[((i>>3)*NNODES + n)*8 + (i&7)];
    __syncthreads();
    if (t < NCO) {
        int c = t >> 4, o = t & 15;
        float w8[8];
#pragma unroll
        for (int i = 0; i < 8; i++) w8[i] = sw[(c*8+i)*16 + o];
        for (int bb = 0; bb < 64; bb++) {
            float a = 0.f;
#pragma unroll
            for (int i = 0; i < 8; i++) a += su[bb*8+i]*w8[i];
            g_priors[bb*PRI_STRIDE + n*NCO + t] = a;
        }
    }
}

// ------- pass A: s0 = (1/43) * sum_n priors; squash -> g_outv -------
__global__ void __launch_bounds__(128) k_passA() {
    int c = blockIdx.x, b = blockIdx.y, t = threadIdx.x;
    int o = t & 15, g = t >> 4;
    float a = 0.f;
    for (int n = g; n < NNODES; n += 8)
        a += g_priors[b*PRI_STRIDE + n*NCO + c*16 + o];
    __shared__ float sr[128];
    sr[t] = a;
    __syncthreads();
    if (t < 16) {
        float s = 0.f;
#pragma unroll
        for (int gg = 0; gg < 8; gg++) s += sr[gg*16 + t];
        s *= (1.f/43.f);
        float sn = s*s;
        sn += __shfl_xor_sync(0xffffu, sn, 8, 16);
        sn += __shfl_xor_sync(0xffffu, sn, 4, 16);
        sn += __shfl_xor_sync(0xffffu, sn, 2, 16);
        sn += __shfl_xor_sync(0xffffu, sn, 1, 16);
        g_outv[(b*43 + c)*16 + t] = s * (sqrtf(sn)/(1.f+sn));
    }
}

// ------- routing pass (B: FIRST=true writes delta0; C: FIRST=false adds it) ----
template<bool FIRST>
__global__ void __launch_bounds__(704) k_route() {
    const int ch = blockIdx.x, b = blockIdx.y, t = threadIdx.x;
    const int c = t >> 4, o = t & 15;
    const bool v = t < NCO;
    __shared__ float sd[43];
    __shared__ float sp[43];
    float ov = v ? g_outv[b*NCO + t] : 0.f;  // current outputs (b,c,o)
    float sacc = 0.f;
    const int n0 = ch * 81;
    for (int nn = 0; nn < 81; nn++) {
        int n = n0 + nn;
        float pr = v ? g_priors[b*PRI_STRIDE + n*NCO + t] : 0.f;
        float w = pr * ov;
        w += __shfl_xor_sync(0xffffffffu, w, 8, 16);
        w += __shfl_xor_sync(0xffffffffu, w, 4, 16);
        w += __shfl_xor_sync(0xffffffffu, w, 2, 16);
        w += __shfl_xor_sync(0xffffffffu, w, 1, 16);
        if (v && o == 0) {
            if (FIRST) { sd[c] = w; g_delta0[(b*NNODES + n)*NCLS + c] = w; }
            else       { sd[c] = w + g_delta0[(b*NNODES + n)*NCLS + c]; }
        }
        __syncthreads();
        if (t < 32) {   // warp0: softmax over 43 classes
            float d1 = (t < 43)      ? sd[t]    : -1e30f;
            float d2 = (t + 32 < 43) ? sd[t+32] : -1e30f;
            float mx = fmaxf(d1, d2);
#pragma unroll
            for (int mm = 16; mm >= 1; mm >>= 1) mx = fmaxf(mx, __shfl_xor_sync(0xffffffffu, mx, mm));
            float e1 = (t < 43)      ? __expf(d1 - mx) : 0.f;
            float e2 = (t + 32 < 43) ? __expf(d2 - mx) : 0.f;
            float sm = e1 + e2;
#pragma unroll
            for (int mm = 16; mm >= 1; mm >>= 1) sm += __shfl_xor_sync(0xffffffffu, sm, mm);
            float inv = 1.f / sm;
            if (t < 43)      sp[t]    = e1 * inv;
            if (t + 32 < 43) sp[t+32] = e2 * inv;
        }
        __syncthreads();
        if (v) sacc += sp[c] * pr;
        __syncthreads();   // protect sd/sp before next iteration overwrites
    }
    if (v) g_part[(b*16 + ch)*NCO + t] = sacc;
}

// ------- reduce partials -> squash -> g_outv (after pass B) -------
__global__ void __launch_bounds__(704) k_reduceB() {
    int b = blockIdx.x, t = threadIdx.x;
    bool v = t < NCO;
    float s = 0.f;
    if (v) {
#pragma unroll
        for (int ch = 0; ch < 16; ch++) s += g_part[(b*16+ch)*NCO + t];
    }
    float sn = s*s;
    sn += __shfl_xor_sync(0xffffffffu, sn, 8, 16);
    sn += __shfl_xor_sync(0xffffffffu, sn, 4, 16);
    sn += __shfl_xor_sync(0xffffffffu, sn, 2, 16);
    sn += __shfl_xor_sync(0xffffffffu, sn, 1, 16);
    if (v) g_outv[b*NCO + t] = s * (sqrtf(sn)/(1.f+sn));
}

// ------- final: scores = ||squash(s2)|| = sn/(1+sn) -------
__global__ void __launch_bounds__(704) k_reduceC(float* __restrict__ out) {
    int b = blockIdx.x, t = threadIdx.x;
    bool v = t < NCO;
    float s = 0.f;
    if (v) {
#pragma unroll
        for (int ch = 0; ch < 16; ch++) s += g_part[(b*16+ch)*NCO + t];
    }
    float sn = s*s;
    sn += __shfl_xor_sync(0xffffffffu, sn, 8, 16);
    sn += __shfl_xor_sync(0xffffffffu, sn, 4, 16);
    sn += __shfl_xor_sync(0xffffffffu, sn, 2, 16);
    sn += __shfl_xor_sync(0xffffffffu, sn, 1, 16);
    if (v && (t & 15) == 0) out[b*43 + (t >> 4)] = sn / (1.f + sn);
}

extern "C" void kernel_launch(void* const* d_in, const int* in_sizes, int n_in,
                              void* d_out, int out_size) {
    const float* x  = (const float*)d_in[0];
    const float* cw = (const float*)d_in[1];
    const float* cb = (const float*)d_in[2];
    const float* pw = (const float*)d_in[3];
    const float* pb = (const float*)d_in[4];
    const float* rw = (const float*)d_in[5];
    float* out = (float*)d_out;

    k_tcw<<<243, 256>>>(cw);
    k_tpw<<<8192, 256>>>(pw);
    k_conv1<<<dim3(24, 64), 256>>>(x, cb);
    k_prim<<<162, 256>>>(pb);
    k_priors<<<1296, 704>>>(rw);
    k_passA<<<dim3(43, 64), 128>>>();
    k_route<true><<<dim3(16, 64), 704>>>();
    k_reduceB<<<64, 704>>>();
    k_route<false><<<dim3(16, 64), 704>>>();
    k_reduceC<<<64, 704>>>(out);
}

// round 3
// speedup vs baseline: 1.9402x; 1.9402x over previous
#include <cuda_runtime.h>
#include <cuda_fp16.h>
#include <cstdint>
#include <math.h>

#define NB 64
#define NNODES 1296
#define NCLS 43
#define ODIM 16
#define NCO 688                 // 43*16
#define PRI_STRIDE (NNODES*NCO) // 891648

// ---------------- scratch (static device arrays; no allocation) ----------------
__device__ float  g_cw[62208];                       // conv1_w transposed [c][ky][kx][oc]
__device__ __align__(16) __half g_pw16[2097152];     // prim_w fp16 [k=(ky*8+kx)*256+ic][oc]
__device__ __align__(16) __half g_h16[9437184];      // conv1 out fp16 NHWC [b][y][x][oc]
__device__ float  g_pp[4 * 5184 * 128];              // split-K partials [sk][m][n]
__device__ float  g_u[NB*NNODES*8];                  // squashed primary caps [b][node][i]
__device__ float  g_priors[57065472];                // [b][n][c][o]  (228 MB)
__device__ float  g_outv[NB*NCO];                    // outputs vector (b, c, o)
__device__ float  g_delta0[NB*NNODES*NCLS];
__device__ float  g_part[NB*16*NCO];                 // per-chunk partial sums of s

// ---------------- mma / ldmatrix primitives ----------------
__device__ __forceinline__ uint32_t smem_u32(const void* p) {
    uint32_t a;
    asm volatile("{ .reg .u64 t; cvta.to.shared.u64 t, %1; cvt.u32.u64 %0, t; }"
                 : "=r"(a) : "l"(p));
    return a;
}
__device__ __forceinline__ void ldm_x4(uint32_t& r0, uint32_t& r1, uint32_t& r2, uint32_t& r3, uint32_t addr) {
    asm volatile("ldmatrix.sync.aligned.m8n8.x4.shared.b16 {%0,%1,%2,%3},[%4];"
                 : "=r"(r0), "=r"(r1), "=r"(r2), "=r"(r3) : "r"(addr));
}
__device__ __forceinline__ void ldm_x4t(uint32_t& r0, uint32_t& r1, uint32_t& r2, uint32_t& r3, uint32_t addr) {
    asm volatile("ldmatrix.sync.aligned.m8n8.x4.trans.shared.b16 {%0,%1,%2,%3},[%4];"
                 : "=r"(r0), "=r"(r1), "=r"(r2), "=r"(r3) : "r"(addr));
}
__device__ __forceinline__ void mma16816(float* c, const uint32_t* a, const uint32_t* b) {
    asm volatile("mma.sync.aligned.m16n8k16.row.col.f32.f16.f16.f32 "
                 "{%0,%1,%2,%3},{%4,%5,%6,%7},{%8,%9},{%0,%1,%2,%3};"
                 : "+f"(c[0]), "+f"(c[1]), "+f"(c[2]), "+f"(c[3])
                 : "r"(a[0]), "r"(a[1]), "r"(a[2]), "r"(a[3]), "r"(b[0]), "r"(b[1]));
}

// ---------------- weight transposes ----------------
__global__ void k_tcw(const float* __restrict__ w) {
    int i = blockIdx.x*256 + threadIdx.x;
    if (i < 62208) {
        int kx = i % 9, t1 = i / 9;
        int ky = t1 % 9, t2 = t1 / 9;
        int c  = t2 % 3, oc = t2 / 3;
        g_cw[((c*9+ky)*9+kx)*256 + oc] = w[i];
    }
}
__global__ void k_tpw(const float* __restrict__ w) {
    int i = blockIdx.x*256 + threadIdx.x;
    if (i < 2097152) {
        int kx = i & 7, ky = (i >> 3) & 7, ic = (i >> 6) & 255, oc = i >> 14;
        g_pw16[(((ky*8+kx) << 8) + ic)*128 + oc] = __float2half(w[i]);
    }
}

// ---------------- conv1: 9x9 valid, relu. block=(y,b), thread=oc ----------------
__global__ void __launch_bounds__(256) k_conv1(const float* __restrict__ x,
                                               const float* __restrict__ cb) {
    const int y = blockIdx.x, b = blockIdx.y, oc = threadIdx.x;
    __shared__ float si[864];   // 3 ch x 9 rows x 32 cols
    for (int i = threadIdx.x; i < 864; i += 256) {
        int c = i / 288, rm = i % 288, r = rm >> 5, col = rm & 31;
        si[i] = x[((b*3 + c)*32 + (y + r))*32 + col];
    }
    __syncthreads();
    float acc[24];
#pragma unroll
    for (int i = 0; i < 24; i++) acc[i] = 0.f;
#pragma unroll 1
    for (int cky = 0; cky < 27; cky++) {        // cky = c*9+ky
        float w[9];
#pragma unroll
        for (int kx = 0; kx < 9; kx++) w[kx] = g_cw[(cky*9+kx)*256 + oc];
        float im[32];
        const float* rp = &si[cky*32];
#pragma unroll
        for (int j = 0; j < 32; j++) im[j] = rp[j];
#pragma unroll
        for (int xx = 0; xx < 24; xx++)
#pragma unroll
            for (int kx = 0; kx < 9; kx++) acc[xx] += w[kx]*im[xx+kx];
    }
    float bb = cb[oc];
#pragma unroll
    for (int xx = 0; xx < 24; xx++)
        g_h16[((b*24+y)*24+xx)*256 + oc] = __float2half(fmaxf(acc[xx] + bb, 0.f));
}

// ------- prim conv as tensor-core implicit GEMM --------
// M=5184 (b,oy,ox), N=128 (oc), K=16384 (ky,kx,ic). Split-K=4 over blockIdx.y.
// Block tile 64x128, BK=64, 8 warps in 2x4, each warp 32x32.
#define LOADA(it) { \
    int k0 = kbase + (it)*64; \
    int pix = k0 >> 8, ic0 = k0 & 255; \
    int ky = pix >> 3, kx = pix & 7; \
    const __half* p = &g_h16[(((ab*24 + 2*aoy + ky)*24 + 2*aox + kx) << 8) + ic0 + ac*8]; \
    ra[0] = *(const uint4*)p; \
    ra[1] = *(const uint4*)(p + 8); \
}
#define LOADB(it) { \
    int k0 = kbase + (it)*64; \
    _Pragma("unroll") \
    for (int j = 0; j < 4; j++) { \
        int id = t + j*256; \
        int rr = id >> 4, cc = id & 15; \
        rb[j] = *(const uint4*)&g_pw16[(k0 + rr)*128 + cc*8]; \
    } \
}
#define STOREAB(buf) { \
    _Pragma("unroll") \
    for (int j = 0; j < 2; j++) { \
        int c = ac + j; \
        *(uint4*)&sA[buf][ar*64 + ((c ^ (ar & 7)) * 8)] = ra[j]; \
    } \
    _Pragma("unroll") \
    for (int j = 0; j < 4; j++) { \
        int id = t + j*256; \
        int rr = id >> 4, cc = id & 15; \
        *(uint4*)&sB[buf][rr*128 + ((cc ^ (rr & 7)) * 8)] = rb[j]; \
    } \
}

__global__ void __launch_bounds__(256) k_prim_tc() {
    const int t = threadIdx.x;
    const int w = t >> 5, l = t & 31;
    const int m0 = blockIdx.x * 64;
    const int kbase = blockIdx.y * 4096;

    __shared__ __align__(16) __half sA[2][64*64];
    __shared__ __align__(16) __half sB[2][64*128];

    // A global-load mapping: each thread loads 2x 16B chunks of one row
    const int ar  = t >> 2;          // tile row 0..63
    const int ac  = (t & 3) * 2;     // chunk-pair base (chunks of 8 halves)
    const int am  = m0 + ar;
    const int ab  = am / 81;
    const int arr = am % 81;
    const int aoy = arr / 9, aox = arr % 9;

    const int wm = w & 1, wn = w >> 1;

    float acc[2][4][4];
#pragma unroll
    for (int i = 0; i < 2; i++)
#pragma unroll
        for (int j = 0; j < 4; j++)
#pragma unroll
            for (int q = 0; q < 4; q++) acc[i][j][q] = 0.f;

    uint4 ra[2], rb[4];

    // prologue
    LOADA(0); LOADB(0);
    STOREAB(0);
    LOADA(1); LOADB(1);
    __syncthreads();

    const uint32_t sa0 = smem_u32(&sA[0][0]);
    const uint32_t sb0 = smem_u32(&sB[0][0]);

    for (int it = 0; it < 64; it++) {
        const int cbuf = it & 1;
        if (it + 1 < 64) { STOREAB((it + 1) & 1); }
        if (it + 2 < 64) { LOADA(it + 2); LOADB(it + 2); }

        const uint32_t sa_u = sa0 + cbuf * (64*64*2);
        const uint32_t sb_u = sb0 + cbuf * (64*128*2);
#pragma unroll
        for (int ks = 0; ks < 4; ks++) {
            uint32_t a[2][4];
#pragma unroll
            for (int ai = 0; ai < 2; ai++) {
                int r = wm*32 + ai*16 + (l & 15);
                int c = ks*2 + (l >> 4);
                uint32_t addr = sa_u + (uint32_t)(r*64 + ((c ^ (r & 7)) * 8)) * 2u;
                ldm_x4(a[ai][0], a[ai][1], a[ai][2], a[ai][3], addr);
            }
            uint32_t bf[4][2];
#pragma unroll
            for (int bp = 0; bp < 2; bp++) {
                int r = ks*16 + (l & 15);
                int c = wn*4 + bp*2 + (l >> 4);
                uint32_t addr = sb_u + (uint32_t)(r*128 + ((c ^ (r & 7)) * 8)) * 2u;
                uint32_t q0, q1, q2, q3;
                ldm_x4t(q0, q1, q2, q3, addr);
                bf[bp*2][0]   = q0; bf[bp*2][1]   = q1;
                bf[bp*2+1][0] = q2; bf[bp*2+1][1] = q3;
            }
#pragma unroll
            for (int ai = 0; ai < 2; ai++)
#pragma unroll
                for (int bi = 0; bi < 4; bi++)
                    mma16816(acc[ai][bi], a[ai], bf[bi]);
        }
        __syncthreads();
    }

    // epilogue: write split-K partials
    const int skb = blockIdx.y * 5184;
#pragma unroll
    for (int ai = 0; ai < 2; ai++) {
#pragma unroll
        for (int bi = 0; bi < 4; bi++) {
            int mrow = m0 + wm*32 + ai*16 + (l >> 2);
            int ncol = wn*32 + bi*8 + (l & 3)*2;
            *(float2*)&g_pp[(skb + mrow)*128 + ncol]     = make_float2(acc[ai][bi][0], acc[ai][bi][1]);
            *(float2*)&g_pp[(skb + mrow + 8)*128 + ncol] = make_float2(acc[ai][bi][2], acc[ai][bi][3]);
        }
    }
}

// ------- reduce split-K partials + bias + squash -> g_u -------
__global__ void __launch_bounds__(256) k_psquash(const float* __restrict__ pbv) {
    int idx = blockIdx.x*256 + threadIdx.x;  // 5184*16 = 82944
    int m = idx >> 4, d = idx & 15;
    float p[8]; float sn = 0.f;
#pragma unroll
    for (int i = 0; i < 8; i++) {
        float s = pbv[i*16 + d];
#pragma unroll
        for (int sk = 0; sk < 4; sk++) s += g_pp[(sk*5184 + m)*128 + i*16 + d];
        p[i] = s; sn += s*s;
    }
    float sc = sqrtf(sn) / (1.f + sn);
    int b = m / 81, rr = m % 81;
    float* up = &g_u[((b*NNODES) + d*81 + rr)*8];
    *(float4*)up       = make_float4(p[0]*sc, p[1]*sc, p[2]*sc, p[3]*sc);
    *(float4*)(up + 4) = make_float4(p[4]*sc, p[5]*sc, p[6]*sc, p[7]*sc);
}

// ------- priors[b,n,c,o] = sum_i u[b,n,i] * W[n,c,i,o]; block per node -------
__global__ void __launch_bounds__(704) k_priors(const float* __restrict__ rw) {
    int n = blockIdx.x, t = threadIdx.x;
    __shared__ float su[512];    // u for all 64 b at this node
    __shared__ float sw[5504];   // W slice [c][i][o]
    for (int i = t; i < 5504; i += 704) sw[i] = rw[n*5504 + i];
    for (int i = t; i < 512;  i += 704) su[i] = g_u[((i>>3)*NNODES + n)*8 + (i&7)];
    __syncthreads();
    if (t < NCO) {
        int c = t >> 4, o = t & 15;
        float w8[8];
#pragma unroll
        for (int i = 0; i < 8; i++) w8[i] = sw[(c*8+i)*16 + o];
        for (int bb = 0; bb < 64; bb++) {
            float a = 0.f;
#pragma unroll
            for (int i = 0; i < 8; i++) a += su[bb*8+i]*w8[i];
            g_priors[bb*PRI_STRIDE + n*NCO + t] = a;
        }
    }
}

// ------- pass A: s0 = (1/43) * sum_n priors; squash -> g_outv -------
__global__ void __launch_bounds__(128) k_passA() {
    int c = blockIdx.x, b = blockIdx.y, t = threadIdx.x;
    int o = t & 15, g = t >> 4;
    float a = 0.f;
    for (int n = g; n < NNODES; n += 8)
        a += g_priors[b*PRI_STRIDE + n*NCO + c*16 + o];
    __shared__ float sr[128];
    sr[t] = a;
    __syncthreads();
    if (t < 16) {
        float s = 0.f;
#pragma unroll
        for (int gg = 0; gg < 8; gg++) s += sr[gg*16 + t];
        s *= (1.f/43.f);
        float sn = s*s;
        sn += __shfl_xor_sync(0xffffu, sn, 8, 16);
        sn += __shfl_xor_sync(0xffffu, sn, 4, 16);
        sn += __shfl_xor_sync(0xffffu, sn, 2, 16);
        sn += __shfl_xor_sync(0xffffu, sn, 1, 16);
        g_outv[(b*43 + c)*16 + t] = s * (sqrtf(sn)/(1.f+sn));
    }
}

// ------- routing pass (B: FIRST=true writes delta0; C: FIRST=false adds it) ----
template<bool FIRST>
__global__ void __launch_bounds__(704) k_route() {
    const int ch = blockIdx.x, b = blockIdx.y, t = threadIdx.x;
    const int c = t >> 4, o = t & 15;
    const bool v = t < NCO;
    __shared__ float sd[43];
    __shared__ float sp[43];
    float ov = v ? g_outv[b*NCO + t] : 0.f;  // current outputs (b,c,o)
    float sacc = 0.f;
    const int n0 = ch * 81;
    for (int nn = 0; nn < 81; nn++) {
        int n = n0 + nn;
        float pr = v ? g_priors[b*PRI_STRIDE + n*NCO + t] : 0.f;
        float w = pr * ov;
        w += __shfl_xor_sync(0xffffffffu, w, 8, 16);
        w += __shfl_xor_sync(0xffffffffu, w, 4, 16);
        w += __shfl_xor_sync(0xffffffffu, w, 2, 16);
        w += __shfl_xor_sync(0xffffffffu, w, 1, 16);
        if (v && o == 0) {
            if (FIRST) { sd[c] = w; g_delta0[(b*NNODES + n)*NCLS + c] = w; }
            else       { sd[c] = w + g_delta0[(b*NNODES + n)*NCLS + c]; }
        }
        __syncthreads();
        if (t < 32) {   // warp0: softmax over 43 classes
            float d1 = (t < 43)      ? sd[t]    : -1e30f;
            float d2 = (t + 32 < 43) ? sd[t+32] : -1e30f;
            float mx = fmaxf(d1, d2);
#pragma unroll
            for (int mm = 16; mm >= 1; mm >>= 1) mx = fmaxf(mx, __shfl_xor_sync(0xffffffffu, mx, mm));
            float e1 = (t < 43)      ? __expf(d1 - mx) : 0.f;
            float e2 = (t + 32 < 43) ? __expf(d2 - mx) : 0.f;
            float sm = e1 + e2;
#pragma unroll
            for (int mm = 16; mm >= 1; mm >>= 1) sm += __shfl_xor_sync(0xffffffffu, sm, mm);
            float inv = 1.f / sm;
            if (t < 43)      sp[t]    = e1 * inv;
            if (t + 32 < 43) sp[t+32] = e2 * inv;
        }
        __syncthreads();
        if (v) sacc += sp[c] * pr;
        __syncthreads();   // protect sd/sp before next iteration overwrites
    }
    if (v) g_part[(b*16 + ch)*NCO + t] = sacc;
}

// ------- reduce partials -> squash -> g_outv (after pass B) -------
__global__ void __launch_bounds__(704) k_reduceB() {
    int b = blockIdx.x, t = threadIdx.x;
    bool v = t < NCO;
    float s = 0.f;
    if (v) {
#pragma unroll
        for (int ch = 0; ch < 16; ch++) s += g_part[(b*16+ch)*NCO + t];
    }
    float sn = s*s;
    sn += __shfl_xor_sync(0xffffffffu, sn, 8, 16);
    sn += __shfl_xor_sync(0xffffffffu, sn, 4, 16);
    sn += __shfl_xor_sync(0xffffffffu, sn, 2, 16);
    sn += __shfl_xor_sync(0xffffffffu, sn, 1, 16);
    if (v) g_outv[b*NCO + t] = s * (sqrtf(sn)/(1.f+sn));
}

// ------- final: scores = ||squash(s2)|| = sn/(1+sn) -------
__global__ void __launch_bounds__(704) k_reduceC(float* __restrict__ out) {
    int b = blockIdx.x, t = threadIdx.x;
    bool v = t < NCO;
    float s = 0.f;
    if (v) {
#pragma unroll
        for (int ch = 0; ch < 16; ch++) s += g_part[(b*16+ch)*NCO + t];
    }
    float sn = s*s;
    sn += __shfl_xor_sync(0xffffffffu, sn, 8, 16);
    sn += __shfl_xor_sync(0xffffffffu, sn, 4, 16);
    sn += __shfl_xor_sync(0xffffffffu, sn, 2, 16);
    sn += __shfl_xor_sync(0xffffffffu, sn, 1, 16);
    if (v && (t & 15) == 0) out[b*43 + (t >> 4)] = sn / (1.f + sn);
}

extern "C" void kernel_launch(void* const* d_in, const int* in_sizes, int n_in,
                              void* d_out, int out_size) {
    const float* x  = (const float*)d_in[0];
    const float* cw = (const float*)d_in[1];
    const float* cb = (const float*)d_in[2];
    const float* pw = (const float*)d_in[3];
    const float* pb = (const float*)d_in[4];
    const float* rw = (const float*)d_in[5];
    float* out = (float*)d_out;

    k_tcw<<<243, 256>>>(cw);
    k_tpw<<<8192, 256>>>(pw);
    k_conv1<<<dim3(24, 64), 256>>>(x, cb);
    k_prim_tc<<<dim3(81, 4), 256>>>();
    k_psquash<<<324, 256>>>(pb);
    k_priors<<<1296, 704>>>(rw);
    k_passA<<<dim3(43, 64), 128>>>();
    k_route<true><<<dim3(16, 64), 704>>>();
    k_reduceB<<<64, 704>>>();
    k_route<false><<<dim3(16, 64), 704>>>();
    k_reduceC<<<64, 704>>>(out);
}

// round 4
// speedup vs baseline: 3.2723x; 1.6866x over previous
#include <cuda_runtime.h>
#include <cuda_fp16.h>
#include <cstdint>
#include <math.h>

#define NB 64
#define NNODES 1296
#define NCLS 43
#define NCO 688                 // 43*16
#define PRI_STRIDE (NNODES*NCO) // 891648
#define CHUNK 12
#define NCHUNK 108              // 1296/12

// ---------------- scratch (static device arrays; no allocation) ----------------
__device__ __align__(16) __half g_w116[65536];       // conv1 w fp16 [k(243 pad 256)][oc 256]
__device__ __align__(16) __half g_a16[9437184];      // im2col A [36864][256] fp16
__device__ __align__(16) __half g_pw16[2097152];     // prim_w fp16 [k][oc=128]
__device__ __align__(16) __half g_h16[9437184];      // conv1 out fp16 NHWC [m=36864][256]
__device__ float  g_pp[8 * 5184 * 128];              // prim split-K partials
__device__ float  g_u[NB*NNODES*8];                  // squashed primary caps
__device__ float  g_priors[57065472];                // [b][n][c][o]  (228 MB)
__device__ float  g_outv[NB*NCO];                    // outputs vector (b,c,o)
__device__ float  g_delta0[NB*NNODES*NCLS];          // [b][n][c]
__device__ float  g_part[NB*NCHUNK*NCO];             // per-chunk partial s

// ---------------- mma / ldmatrix primitives ----------------
__device__ __forceinline__ uint32_t smem_u32(const void* p) {
    uint32_t a;
    asm volatile("{ .reg .u64 t; cvta.to.shared.u64 t, %1; cvt.u32.u64 %0, t; }"
                 : "=r"(a) : "l"(p));
    return a;
}
__device__ __forceinline__ void ldm_x4(uint32_t& r0, uint32_t& r1, uint32_t& r2, uint32_t& r3, uint32_t addr) {
    asm volatile("ldmatrix.sync.aligned.m8n8.x4.shared.b16 {%0,%1,%2,%3},[%4];"
                 : "=r"(r0), "=r"(r1), "=r"(r2), "=r"(r3) : "r"(addr));
}
__device__ __forceinline__ void ldm_x4t(uint32_t& r0, uint32_t& r1, uint32_t& r2, uint32_t& r3, uint32_t addr) {
    asm volatile("ldmatrix.sync.aligned.m8n8.x4.trans.shared.b16 {%0,%1,%2,%3},[%4];"
                 : "=r"(r0), "=r"(r1), "=r"(r2), "=r"(r3) : "r"(addr));
}
__device__ __forceinline__ void mma16816(float* c, const uint32_t* a, const uint32_t* b) {
    asm volatile("mma.sync.aligned.m16n8k16.row.col.f32.f16.f16.f32 "
                 "{%0,%1,%2,%3},{%4,%5,%6,%7},{%8,%9},{%0,%1,%2,%3};"
                 : "+f"(c[0]), "+f"(c[1]), "+f"(c[2]), "+f"(c[3])
                 : "r"(a[0]), "r"(a[1]), "r"(a[2]), "r"(a[3]), "r"(b[0]), "r"(b[1]));
}

// ---------------- weight transposes / im2col ----------------
__global__ void k_tw1(const float* __restrict__ w) {
    int i = blockIdx.x*256 + threadIdx.x;     // 65536
    int k = i >> 8, oc = i & 255;
    float v = 0.f;
    if (k < 243) {
        int c = k / 81, r = k % 81, ky = r / 9, kx = r % 9;
        v = w[((oc*3 + c)*9 + ky)*9 + kx];
    }
    g_w116[k*256 + oc] = __float2half(v);
}
__global__ void k_tpw(const float* __restrict__ w) {
    int i = blockIdx.x*256 + threadIdx.x;
    if (i < 2097152) {
        int kx = i & 7, ky = (i >> 3) & 7, ic = (i >> 6) & 255, oc = i >> 14;
        g_pw16[(((ky*8+kx) << 8) + ic)*128 + oc] = __float2half(w[i]);
    }
}
__global__ void k_im2col(const float* __restrict__ x) {
    int m = blockIdx.x, k = threadIdx.x;      // m<36864, k<256
    float v = 0.f;
    if (k < 243) {
        int b = m / 576, r = m % 576, y = r / 24, x0 = r % 24;
        int c = k / 81, rr = k % 81, ky = rr / 9, kx = rr % 9;
        v = x[((b*3 + c)*32 + (y + ky))*32 + (x0 + kx)];
    }
    g_a16[m*256 + k] = __float2half(v);
}

// ---------------- shared GEMM macros (64x128 tile, BK=64, 8 warps 2x4) ---------
#define STOREAB(buf) { \
    _Pragma("unroll") \
    for (int j = 0; j < 2; j++) { \
        int c = ac + j; \
        *(uint4*)&sA[buf][ar*64 + ((c ^ (ar & 7)) * 8)] = ra[j]; \
    } \
    _Pragma("unroll") \
    for (int j = 0; j < 4; j++) { \
        int id = t + j*256; \
        int rr = id >> 4, cc = id & 15; \
        *(uint4*)&sB[buf][rr*128 + ((cc ^ (rr & 7)) * 8)] = rb[j]; \
    } \
}
#define GEMM_BODY(NITER) \
    for (int it = 0; it < (NITER); it++) { \
        const int cbuf = it & 1; \
        if (it + 1 < (NITER)) { STOREAB((it + 1) & 1); } \
        if (it + 2 < (NITER)) { LOADAB(it + 2); } \
        const uint32_t sa_u = sa0 + cbuf * (64*64*2); \
        const uint32_t sb_u = sb0 + cbuf * (64*128*2); \
        _Pragma("unroll") \
        for (int ks = 0; ks < 4; ks++) { \
            uint32_t a[2][4]; \
            _Pragma("unroll") \
            for (int ai = 0; ai < 2; ai++) { \
                int r = wm*32 + ai*16 + (l & 15); \
                int c = ks*2 + (l >> 4); \
                uint32_t addr = sa_u + (uint32_t)(r*64 + ((c ^ (r & 7)) * 8)) * 2u; \
                ldm_x4(a[ai][0], a[ai][1], a[ai][2], a[ai][3], addr); \
            } \
            uint32_t bf[4][2]; \
            _Pragma("unroll") \
            for (int bp = 0; bp < 2; bp++) { \
                int r = ks*16 + (l & 15); \
                int c = wn*4 + bp*2 + (l >> 4); \
                uint32_t addr = sb_u + (uint32_t)(r*128 + ((c ^ (r & 7)) * 8)) * 2u; \
                uint32_t q0, q1, q2, q3; \
                ldm_x4t(q0, q1, q2, q3, addr); \
                bf[bp*2][0]   = q0; bf[bp*2][1]   = q1; \
                bf[bp*2+1][0] = q2; bf[bp*2+1][1] = q3; \
            } \
            _Pragma("unroll") \
            for (int ai = 0; ai < 2; ai++) \
                _Pragma("unroll") \
                for (int bi = 0; bi < 4; bi++) \
                    mma16816(acc[ai][bi], a[ai], bf[bi]); \
        } \
        __syncthreads(); \
    }

// ------- conv1 as GEMM: M=36864, N=256 (2 halves), K=256 (243 padded) ---------
__global__ void __launch_bounds__(256) k_conv1_tc(const float* __restrict__ cb) {
    const int t = threadIdx.x;
    const int w = t >> 5, l = t & 31;
    const int m0 = blockIdx.x * 64;
    const int n0 = blockIdx.y * 128;

    __shared__ __align__(16) __half sA[2][64*64];
    __shared__ __align__(16) __half sB[2][64*128];

    const int ar = t >> 2;
    const int ac = (t & 3) * 2;
    const int am = m0 + ar;
    const int wm = w & 1, wn = w >> 1;

    float acc[2][4][4];
#pragma unroll
    for (int i = 0; i < 2; i++)
#pragma unroll
        for (int j = 0; j < 4; j++)
#pragma unroll
            for (int q = 0; q < 4; q++) acc[i][j][q] = 0.f;

    uint4 ra[2], rb[4];
#define LOADAB(it) { \
    int k0 = (it)*64; \
    ra[0] = *(const uint4*)&g_a16[am*256 + k0 + ac*8]; \
    ra[1] = *(const uint4*)&g_a16[am*256 + k0 + ac*8 + 8]; \
    _Pragma("unroll") \
    for (int j = 0; j < 4; j++) { \
        int id = t + j*256; \
        int rr = id >> 4, cc = id & 15; \
        rb[j] = *(const uint4*)&g_w116[(k0 + rr)*256 + n0 + cc*8]; \
    } \
}
    LOADAB(0);
    STOREAB(0);
    LOADAB(1);
    __syncthreads();
    const uint32_t sa0 = smem_u32(&sA[0][0]);
    const uint32_t sb0 = smem_u32(&sB[0][0]);
    GEMM_BODY(4)
#undef LOADAB

    // epilogue: +bias, relu, fp16 NHWC
#pragma unroll
    for (int ai = 0; ai < 2; ai++) {
#pragma unroll
        for (int bi = 0; bi < 4; bi++) {
            int mrow = m0 + wm*32 + ai*16 + (l >> 2);
            int ncol = n0 + wn*32 + bi*8 + (l & 3)*2;
            float b0 = cb[ncol], b1 = cb[ncol+1];
            float2 v0 = make_float2(fmaxf(acc[ai][bi][0] + b0, 0.f), fmaxf(acc[ai][bi][1] + b1, 0.f));
            float2 v1 = make_float2(fmaxf(acc[ai][bi][2] + b0, 0.f), fmaxf(acc[ai][bi][3] + b1, 0.f));
            *(__half2*)&g_h16[mrow*256 + ncol]       = __floats2half2_rn(v0.x, v0.y);
            *(__half2*)&g_h16[(mrow+8)*256 + ncol]   = __floats2half2_rn(v1.x, v1.y);
        }
    }
}

// ------- prim conv GEMM: M=5184, N=128, K=16384, split-K=8 --------
__global__ void __launch_bounds__(256) k_prim_tc() {
    const int t = threadIdx.x;
    const int w = t >> 5, l = t & 31;
    const int m0 = blockIdx.x * 64;
    const int kbase = blockIdx.y * 2048;

    __shared__ __align__(16) __half sA[2][64*64];
    __shared__ __align__(16) __half sB[2][64*128];

    const int ar  = t >> 2;
    const int ac  = (t & 3) * 2;
    const int am  = m0 + ar;
    const int ab  = am / 81;
    const int arr = am % 81;
    const int aoy = arr / 9, aox = arr % 9;
    const int wm = w & 1, wn = w >> 1;

    float acc[2][4][4];
#pragma unroll
    for (int i = 0; i < 2; i++)
#pragma unroll
        for (int j = 0; j < 4; j++)
#pragma unroll
            for (int q = 0; q < 4; q++) acc[i][j][q] = 0.f;

    uint4 ra[2], rb[4];
#define LOADAB(it) { \
    int k0 = kbase + (it)*64; \
    int pix = k0 >> 8, ic0 = k0 & 255; \
    int ky = pix >> 3, kx = pix & 7; \
    const __half* p = &g_h16[(((ab*24 + 2*aoy + ky)*24 + 2*aox + kx) << 8) + ic0 + ac*8]; \
    ra[0] = *(const uint4*)p; \
    ra[1] = *(const uint4*)(p + 8); \
    _Pragma("unroll") \
    for (int j = 0; j < 4; j++) { \
        int id = t + j*256; \
        int rr = id >> 4, cc = id & 15; \
        rb[j] = *(const uint4*)&g_pw16[(k0 + rr)*128 + cc*8]; \
    } \
}
    LOADAB(0);
    STOREAB(0);
    LOADAB(1);
    __syncthreads();
    const uint32_t sa0 = smem_u32(&sA[0][0]);
    const uint32_t sb0 = smem_u32(&sB[0][0]);
    GEMM_BODY(32)
#undef LOADAB

    const int skb = blockIdx.y * 5184;
#pragma unroll
    for (int ai = 0; ai < 2; ai++) {
#pragma unroll
        for (int bi = 0; bi < 4; bi++) {
            int mrow = m0 + wm*32 + ai*16 + (l >> 2);
            int ncol = wn*32 + bi*8 + (l & 3)*2;
            *(float2*)&g_pp[(skb + mrow)*128 + ncol]     = make_float2(acc[ai][bi][0], acc[ai][bi][1]);
            *(float2*)&g_pp[(skb + mrow + 8)*128 + ncol] = make_float2(acc[ai][bi][2], acc[ai][bi][3]);
        }
    }
}

// ------- reduce split-K + bias + squash -> g_u -------
__global__ void __launch_bounds__(256) k_psquash(const float* __restrict__ pbv) {
    int idx = blockIdx.x*256 + threadIdx.x;  // 82944
    int m = idx >> 4, d = idx & 15;
    float p[8]; float sn = 0.f;
#pragma unroll
    for (int i = 0; i < 8; i++) {
        float s = pbv[i*16 + d];
#pragma unroll
        for (int sk = 0; sk < 8; sk++) s += g_pp[(sk*5184 + m)*128 + i*16 + d];
        p[i] = s; sn += s*s;
    }
    float sc = sqrtf(sn) / (1.f + sn);
    int b = m / 81, rr = m % 81;
    float* up = &g_u[((b*NNODES) + d*81 + rr)*8];
    *(float4*)up       = make_float4(p[0]*sc, p[1]*sc, p[2]*sc, p[3]*sc);
    *(float4*)(up + 4) = make_float4(p[4]*sc, p[5]*sc, p[6]*sc, p[7]*sc);
}

// ------- priors[b,n,c,o] = sum_i u[b,n,i] * W[n,c,i,o]; block per node -------
__global__ void __launch_bounds__(704) k_priors(const float* __restrict__ rw) {
    int n = blockIdx.x, t = threadIdx.x;
    __shared__ float su[512];
    __shared__ float sw[5504];
    for (int i = t; i < 5504; i += 704) sw[i] = rw[n*5504 + i];
    for (int i = t; i < 512;  i += 704) su[i] = g_u[((i>>3)*NNODES + n)*8 + (i&7)];
    __syncthreads();
    if (t < NCO) {
        int c = t >> 4, o = t & 15;
        float w8[8];
#pragma unroll
        for (int i = 0; i < 8; i++) w8[i] = sw[(c*8+i)*16 + o];
        for (int bb = 0; bb < 64; bb++) {
            float a = 0.f;
#pragma unroll
            for (int i = 0; i < 8; i++) a += su[bb*8+i]*w8[i];
            g_priors[bb*PRI_STRIDE + n*NCO + t] = a;
        }
    }
}

// ------- routing pass: block = (chunk of 12 nodes, b). MODE 0=uniform(passA),
// 1=first iter (store delta0), 2=second iter (add delta0). Reads priors ONCE.
template<int MODE>
__global__ void __launch_bounds__(704) k_routeN() {
    const int ch = blockIdx.x, b = blockIdx.y, t = threadIdx.x;
    __shared__ float sp[CHUNK*NCO];   // 33024 B
    __shared__ float sov[NCO];
    __shared__ float sd[CHUNK*NCLS];
    __shared__ float smx[CHUNK];
    __shared__ float sinv[CHUNK];

    // load priors chunk (8256 consecutive floats) as float4
    {
        const float4* src = (const float4*)&g_priors[b*PRI_STRIDE + ch*CHUNK*NCO];
        float4* dst = (float4*)sp;
        for (int i = t; i < CHUNK*NCO/4; i += 704) dst[i] = src[i];
    }
    if (MODE != 0) {
        if (t < NCO) sov[t] = g_outv[b*NCO + t];
    }
    __syncthreads();

    if (MODE != 0) {
        // deltas: thread t<516 -> (n = t/43, c = t%43)
        if (t < CHUNK*NCLS) {
            int n = t / NCLS, c = t % NCLS;
            const float* pr = &sp[n*NCO + c*16];
            const float* ov = &sov[c*16];
            float d = 0.f;
#pragma unroll
            for (int o = 0; o < 16; o++) d += pr[o]*ov[o];
            if (MODE == 1) {
                g_delta0[(b*NNODES + ch*CHUNK + n)*NCLS + c] = d;
            } else {
                d += g_delta0[(b*NNODES + ch*CHUNK + n)*NCLS + c];
            }
            sd[t] = d;
        }
        __syncthreads();
        // softmax (batched over 12 nodes)
        if (t < CHUNK) {
            float mx = -1e30f;
            for (int c = 0; c < NCLS; c++) mx = fmaxf(mx, sd[t*NCLS + c]);
            smx[t] = mx;
        }
        __syncthreads();
        if (t < CHUNK*NCLS) sd[t] = __expf(sd[t] - smx[t / NCLS]);
        __syncthreads();
        if (t < CHUNK) {
            float s = 0.f;
            for (int c = 0; c < NCLS; c++) s += sd[t*NCLS + c];
            sinv[t] = 1.f / s;
        }
        __syncthreads();
    }

    // weighted partial sum over this chunk's nodes
    if (t < NCO) {
        int c = t >> 4;
        float acc = 0.f;
        if (MODE == 0) {
#pragma unroll
            for (int n = 0; n < CHUNK; n++) acc += sp[n*NCO + t];
            acc *= (1.f/43.f);
        } else {
#pragma unroll
            for (int n = 0; n < CHUNK; n++)
                acc += (sd[n*NCLS + c] * sinv[n]) * sp[n*NCO + t];
        }
        g_part[(b*NCHUNK + ch)*NCO + t] = acc;
    }
}

// ------- reduce partials -> squash -> g_outv -------
__global__ void __launch_bounds__(704) k_rsquash() {
    int b = blockIdx.x, t = threadIdx.x;
    bool v = t < NCO;
    float s = 0.f;
    if (v) for (int ch = 0; ch < NCHUNK; ch++) s += g_part[(b*NCHUNK+ch)*NCO + t];
    float sn = s*s;
    sn += __shfl_xor_sync(0xffffffffu, sn, 8, 16);
    sn += __shfl_xor_sync(0xffffffffu, sn, 4, 16);
    sn += __shfl_xor_sync(0xffffffffu, sn, 2, 16);
    sn += __shfl_xor_sync(0xffffffffu, sn, 1, 16);
    if (v) g_outv[b*NCO + t] = s * (sqrtf(sn)/(1.f+sn));
}

// ------- final: scores = sn/(1+sn) -------
__global__ void __launch_bounds__(704) k_rfinal(float* __restrict__ out) {
    int b = blockIdx.x, t = threadIdx.x;
    bool v = t < NCO;
    float s = 0.f;
    if (v) for (int ch = 0; ch < NCHUNK; ch++) s += g_part[(b*NCHUNK+ch)*NCO + t];
    float sn = s*s;
    sn += __shfl_xor_sync(0xffffffffu, sn, 8, 16);
    sn += __shfl_xor_sync(0xffffffffu, sn, 4, 16);
    sn += __shfl_xor_sync(0xffffffffu, sn, 2, 16);
    sn += __shfl_xor_sync(0xffffffffu, sn, 1, 16);
    if (v && (t & 15) == 0) out[b*NCLS + (t >> 4)] = sn / (1.f + sn);
}

extern "C" void kernel_launch(void* const* d_in, const int* in_sizes, int n_in,
                              void* d_out, int out_size) {
    const float* x  = (const float*)d_in[0];
    const float* cw = (const float*)d_in[1];
    const float* cb = (const float*)d_in[2];
    const float* pw = (const float*)d_in[3];
    const float* pb = (const float*)d_in[4];
    const float* rw = (const float*)d_in[5];
    float* out = (float*)d_out;

    k_tw1<<<256, 256>>>(cw);
    k_tpw<<<8192, 256>>>(pw);
    k_im2col<<<36864, 256>>>(x);
    k_conv1_tc<<<dim3(576, 2), 256>>>(cb);
    k_prim_tc<<<dim3(81, 8), 256>>>();
    k_psquash<<<324, 256>>>(pb);
    k_priors<<<1296, 704>>>(rw);
    k_routeN<0><<<dim3(NCHUNK, 64), 704>>>();
    k_rsquash<<<64, 704>>>();
    k_routeN<1><<<dim3(NCHUNK, 64), 704>>>();
    k_rsquash<<<64, 704>>>();
    k_routeN<2><<<dim3(NCHUNK, 64), 704>>>();
    k_rfinal<<<64, 704>>>(out);
}